// round 2
// baseline (speedup 1.0000x reference)
#include <cuda_runtime.h>
#include <cuda_bf16.h>
#include <cstdint>

// ---------------------------------------------------------------------------
// RGCN layer:
//   W[r]      = sum_b w_comp[r,b] * weight[b]          (16 x 128 x 128)
//   H[n,r,o]  = sum_i x[n,i] * W[r,i,o]                (GEMM 100k x 2048, K=128)
//   out[d]    = bias + sum_{e: dst=d} H[src[e], etype[e], :]
// ---------------------------------------------------------------------------

#define MAX_NODES 100000
#define IN_FEAT   128
#define OUT_FEAT  128
#define NUM_RELS  16
#define NUM_BASES 8
#define NCOL      (NUM_RELS * OUT_FEAT)   // 2048

// Scratch (static __device__ globals: allocation-free rule)
__device__ float g_Wb[IN_FEAT * NCOL];                     // B matrix [128][2048]
__device__ float g_H[(size_t)MAX_NODES * NCOL];            // 819.2 MB
__device__ int   g_idx64;                                  // 1 if index arrays are int64

// ---------------------------------------------------------------------------
// Kernel 1: detect whether index arrays are int64 or int32.
// If int64 (values < 2^31, non-negative), every odd 32-bit word is zero.
// ---------------------------------------------------------------------------
__global__ void detect_idx_kernel(const unsigned int* __restrict__ srcw, int n_edges)
{
    __shared__ int nz;
    if (threadIdx.x == 0) nz = 0;
    __syncthreads();
    int samples = n_edges < 2048 ? n_edges : 2048;
    for (int i = threadIdx.x; i < samples; i += blockDim.x) {
        if (srcw[2 * i + 1] != 0u) atomicOr(&nz, 1);
    }
    __syncthreads();
    if (threadIdx.x == 0) g_idx64 = (nz == 0) ? 1 : 0;
}

// ---------------------------------------------------------------------------
// Kernel 2: Wb[i][r*128+o] = sum_b w_comp[r,b] * weight[b,i,o]
// ---------------------------------------------------------------------------
__global__ void prep_W_kernel(const float* __restrict__ weight,
                              const float* __restrict__ w_comp)
{
    int idx = blockIdx.x * blockDim.x + threadIdx.x;
    if (idx >= IN_FEAT * NCOL) return;
    int i = idx >> 11;        // input-feature row (K index)
    int n = idx & (NCOL - 1); // column
    int r = n >> 7;
    int o = n & 127;
    float s = 0.f;
#pragma unroll
    for (int b = 0; b < NUM_BASES; b++)
        s += w_comp[r * NUM_BASES + b] * weight[((b * IN_FEAT) + i) * OUT_FEAT + o];
    g_Wb[idx] = s;
}

// ---------------------------------------------------------------------------
// Kernel 3: fp32 GEMM via packed fma.rn.f32x2.
//   C[M x 2048] = A[M x 128] * Wb[128 x 2048]
// BM=128, BN=128, BK=8, thread tile 8x8, 256 threads.
// A tile stored REPLICATED in SMEM ({m,m} pairs) so the broadcast operand of
// the packed FMA is a single 8-byte shared load.
// ---------------------------------------------------------------------------
#define BM 128
#define BN 128
#define BK 8
#define TM 8
#define TN 8

__device__ __forceinline__ void fma2(unsigned long long& d,
                                     unsigned long long a,
                                     unsigned long long b)
{
    asm("fma.rn.f32x2 %0, %1, %2, %0;" : "+l"(d) : "l"(a), "l"(b));
}

__global__ __launch_bounds__(256, 2) void sgemm_f32x2_kernel(
    const float* __restrict__ A,   // x: M x 128
    float* __restrict__ C,         // g_H: M x 2048
    int M)
{
    __shared__ float As2[BK][2 * BM];  // replicated A, 8 KB
    __shared__ float Bs[BK][BN];       // 4 KB

    const int tid  = threadIdx.x;
    const int cCol = blockIdx.x;            // 0..15
    const int cRow = blockIdx.y;            // 0..ceil(M/128)-1
    const int rowBase = cRow * BM;

    // A tile loads: 128 rows x 8 k -> 256 float4 (one per thread)
    const int aRow = tid >> 1;              // 0..127
    const int aCol = (tid & 1) * 4;         // 0 or 4
    // B tile loads: 8 rows x 128 cols -> 256 float4
    const int bRow = tid >> 5;              // 0..7
    const int bCol = (tid & 31) * 4;        // 0..124

    const int threadRow = (tid >> 4) * TM;  // 0..120
    const int threadCol = (tid & 15) * TN;  // 0..120

    const float* Ab = A + (size_t)rowBase * IN_FEAT;
    const float* Bb = g_Wb + cCol * BN;

    unsigned long long acc[TM][TN / 2];
#pragma unroll
    for (int i = 0; i < TM; i++)
#pragma unroll
        for (int j = 0; j < TN / 2; j++) acc[i][j] = 0ull;

    for (int k0 = 0; k0 < IN_FEAT; k0 += BK) {
        // --- load A (bounds-checked on M), replicate each value twice ---
        float4 a4 = make_float4(0.f, 0.f, 0.f, 0.f);
        if (rowBase + aRow < M)
            a4 = *(const float4*)(Ab + (size_t)aRow * IN_FEAT + k0 + aCol);
        As2[aCol + 0][2 * aRow] = a4.x;  As2[aCol + 0][2 * aRow + 1] = a4.x;
        As2[aCol + 1][2 * aRow] = a4.y;  As2[aCol + 1][2 * aRow + 1] = a4.y;
        As2[aCol + 2][2 * aRow] = a4.z;  As2[aCol + 2][2 * aRow + 1] = a4.z;
        As2[aCol + 3][2 * aRow] = a4.w;  As2[aCol + 3][2 * aRow + 1] = a4.w;
        // --- load B (always in bounds: K=128, N=2048 exact) ---
        *(float4*)&Bs[bRow][bCol] =
            *(const float4*)(Bb + (size_t)(k0 + bRow) * NCOL + bCol);
        __syncthreads();

#pragma unroll
        for (int k = 0; k < BK; k++) {
            unsigned long long rM[TM];
            unsigned long long rN[TN / 2];
#pragma unroll
            for (int i = 0; i < TM; i++)
                rM[i] = *(const unsigned long long*)&As2[k][2 * (threadRow + i)];
#pragma unroll
            for (int j = 0; j < TN / 2; j++)
                rN[j] = *(const unsigned long long*)&Bs[k][threadCol + 2 * j];
#pragma unroll
            for (int i = 0; i < TM; i++)
#pragma unroll
                for (int j = 0; j < TN / 2; j++)
                    fma2(acc[i][j], rM[i], rN[j]);
        }
        __syncthreads();
    }

    // --- epilogue ---
    float* Cb = C + (size_t)rowBase * NCOL + cCol * BN;
#pragma unroll
    for (int i = 0; i < TM; i++) {
        if (rowBase + threadRow + i < M) {
            float c[8];
#pragma unroll
            for (int j = 0; j < TN / 2; j++) {
                float lo, hi;
                asm("mov.b64 {%0,%1}, %2;" : "=f"(lo), "=f"(hi) : "l"(acc[i][j]));
                c[2 * j] = lo; c[2 * j + 1] = hi;
            }
            float* dst = Cb + (size_t)(threadRow + i) * NCOL + threadCol;
            *(float4*)(dst)     = make_float4(c[0], c[1], c[2], c[3]);
            *(float4*)(dst + 4) = make_float4(c[4], c[5], c[6], c[7]);
        }
    }
}

// ---------------------------------------------------------------------------
// Kernel 4: out[n, :] = bias
// ---------------------------------------------------------------------------
__global__ void init_out_kernel(float* __restrict__ out,
                                const float* __restrict__ bias,
                                int n_nodes)
{
    __shared__ float4 b4[OUT_FEAT / 4];
    if (threadIdx.x < OUT_FEAT / 4)
        b4[threadIdx.x] = ((const float4*)bias)[threadIdx.x];
    __syncthreads();
    size_t total = (size_t)n_nodes * (OUT_FEAT / 4);
    for (size_t i = (size_t)blockIdx.x * blockDim.x + threadIdx.x; i < total;
         i += (size_t)gridDim.x * blockDim.x)
        ((float4*)out)[i] = b4[i & (OUT_FEAT / 4 - 1)];
}

// ---------------------------------------------------------------------------
// Kernel 5: warp-per-edge gather + vectorized atomic scatter.
//   msg = H[src, etype, :]  (512B contiguous per edge)
//   out[dst, :] += msg      (red.global.add.v4.f32)
// ---------------------------------------------------------------------------
__global__ __launch_bounds__(256) void edge_scatter_kernel(
    const void* __restrict__ srcp,
    const void* __restrict__ dstp,
    const void* __restrict__ etp,
    float* __restrict__ out,
    int n_edges)
{
    int gw = (blockIdx.x * 256 + threadIdx.x) >> 5;   // global warp id = edge id
    if (gw >= n_edges) return;
    int lane = threadIdx.x & 31;

    int s, d, t;
    if (g_idx64) {
        s = (int)((const long long*)srcp)[gw];
        d = (int)((const long long*)dstp)[gw];
        t = (int)((const long long*)etp)[gw];
    } else {
        s = ((const int*)srcp)[gw];
        d = ((const int*)dstp)[gw];
        t = ((const int*)etp)[gw];
    }

    const float4 v = __ldg(
        (const float4*)(g_H + ((size_t)s * NUM_RELS + t) * OUT_FEAT) + lane);
    float* o = out + (size_t)d * OUT_FEAT + lane * 4;
    asm volatile("red.global.add.v4.f32 [%0], {%1,%2,%3,%4};"
                 :: "l"(o), "f"(v.x), "f"(v.y), "f"(v.z), "f"(v.w)
                 : "memory");
}

// ---------------------------------------------------------------------------
// launch
// Inputs (metadata order): 0:x  1:weight  2:w_comp  3:h_bias  4:src  5:dst  6:etypes
// ---------------------------------------------------------------------------
extern "C" void kernel_launch(void* const* d_in, const int* in_sizes, int n_in,
                              void* d_out, int out_size)
{
    const float* x      = (const float*)d_in[0];
    const float* weight = (const float*)d_in[1];
    const float* w_comp = (const float*)d_in[2];
    const float* bias   = (const float*)d_in[3];
    const void*  src    = d_in[4];
    const void*  dst    = d_in[5];
    const void*  et     = d_in[6];
    float* out          = (float*)d_out;

    int n_nodes = in_sizes[0] / IN_FEAT;
    int n_edges = in_sizes[4];

    // 1. index-dtype detection (int64 vs int32)
    detect_idx_kernel<<<1, 256>>>((const unsigned int*)src, n_edges);

    // 2. per-relation weight matrix (as GEMM B operand)
    prep_W_kernel<<<(IN_FEAT * NCOL + 255) / 256, 256>>>(weight, w_comp);

    // 3. H = x @ Wb
    {
        float* H;
        cudaGetSymbolAddress((void**)&H, g_H);
        dim3 grid(NCOL / BN, (n_nodes + BM - 1) / BM);
        sgemm_f32x2_kernel<<<grid, 256>>>(x, H, n_nodes);
    }

    // 4. out = bias (broadcast)
    init_out_kernel<<<1024, 256>>>(out, bias, n_nodes);

    // 5. gather + scatter-add over edges
    {
        int warps_per_cta = 8;
        int blocks = (n_edges + warps_per_cta - 1) / warps_per_cta;
        edge_scatter_kernel<<<blocks, 256>>>(src, dst, et, out, n_edges);
    }
}

// round 4
// speedup vs baseline: 1.5299x; 1.5299x over previous
#include <cuda_runtime.h>
#include <cuda_bf16.h>
#include <cstdint>

// ---------------------------------------------------------------------------
// RGCN layer, basis-factored:
//   y[n,b,o]  = sum_i x[n,i] * weight[b,i,o]      GEMM 100k x 1024, K=128 (half FLOPs)
//   H[n,r,o]  = sum_b w_comp[r,b] * y[n,b,o]      memory-bound recombination
//   out[d]    = bias + sum_{e: dst=d} H[src[e], etype[e], :]
// (tcgen05 unavailable: harness ptxas targets sm_103 without the 'a' suffix)
// ---------------------------------------------------------------------------

#define MAX_NODES 100000
#define IN_FEAT   128
#define OUT_FEAT  128
#define NUM_RELS  16
#define NUM_BASES 8
#define NCOL      (NUM_RELS * OUT_FEAT)    // 2048
#define NB        (NUM_BASES * OUT_FEAT)   // 1024

// Scratch (static __device__ globals: allocation-free rule)
__device__ float g_Wbb[IN_FEAT * NB];                 // B matrix [128][1024] (k-major)
__device__ float g_Y[(size_t)MAX_NODES * NB];         // 409.6 MB
__device__ float g_H[(size_t)MAX_NODES * NCOL];       // 819.2 MB
__device__ int   g_idx64;                             // 1 if index arrays are int64

// ---------------------------------------------------------------------------
// Kernel 1: detect whether index arrays are int64 or int32.
// ---------------------------------------------------------------------------
__global__ void detect_idx_kernel(const unsigned int* __restrict__ srcw, int n_edges)
{
    __shared__ int nz;
    if (threadIdx.x == 0) nz = 0;
    __syncthreads();
    int samples = n_edges < 2048 ? n_edges : 2048;
    for (int i = threadIdx.x; i < samples; i += blockDim.x)
        if (srcw[2 * i + 1] != 0u) atomicOr(&nz, 1);
    __syncthreads();
    if (threadIdx.x == 0) g_idx64 = (nz == 0) ? 1 : 0;
}

// ---------------------------------------------------------------------------
// Kernel 2: transpose-pack basis weights: Wbb[k][b*128+o] = weight[b,k,o]
// ---------------------------------------------------------------------------
__global__ void prep_Wbb_kernel(const float* __restrict__ weight)
{
    int idx = blockIdx.x * blockDim.x + threadIdx.x;
    if (idx >= IN_FEAT * NB) return;
    int k = idx >> 10;          // 0..127
    int n = idx & (NB - 1);     // 0..1023
    int b = n >> 7;
    int o = n & 127;
    g_Wbb[idx] = weight[((b * IN_FEAT) + k) * OUT_FEAT + o];
}

// ---------------------------------------------------------------------------
// Kernel 3: fp32 GEMM via packed fma.rn.f32x2.
//   Y[M x 1024] = A[M x 128] * Wbb[128 x 1024]
// BM=128, BN=128, BK=8, thread tile 8x8, 256 threads.
// A tile replicated in SMEM ({m,m} pairs -> broadcast LDS.64).
// Each thread's 8 columns are 4 pairs at stride 32 (col = 2*(tid&15) + p*32)
// so the rN LDS.64 across lanes 0..15 covers 128 contiguous bytes: conflict-free.
// ---------------------------------------------------------------------------
#define BM 128
#define BN 128
#define BK 8
#define TM 8

__device__ __forceinline__ void fma2(unsigned long long& d,
                                     unsigned long long a,
                                     unsigned long long b)
{
    asm("fma.rn.f32x2 %0, %1, %2, %0;" : "+l"(d) : "l"(a), "l"(b));
}

__global__ __launch_bounds__(256, 2) void sgemm_y_kernel(
    const float* __restrict__ A,   // x: M x 128
    int M)
{
    __shared__ float As2[BK][2 * BM];  // replicated A, 8 KB
    __shared__ float Bs[BK][BN];       // 4 KB

    const int tid  = threadIdx.x;
    const int cCol = blockIdx.x;            // 0..7
    const int rowBase = blockIdx.y * BM;

    const int aRow = tid >> 1;              // 0..127
    const int aCol = (tid & 1) * 4;         // 0 or 4
    const int bRow = tid >> 5;              // 0..7
    const int bCol = (tid & 31) * 4;        // 0..124

    const int threadRow = (tid >> 4) * TM;  // 0..120
    const int pairCol   = 2 * (tid & 15);   // 0..30  (pair p lives at pairCol + 32p)

    const float* Ab = A + (size_t)rowBase * IN_FEAT;
    const float* Bb = g_Wbb + cCol * BN;

    unsigned long long acc[TM][4];
#pragma unroll
    for (int i = 0; i < TM; i++)
#pragma unroll
        for (int p = 0; p < 4; p++) acc[i][p] = 0ull;

    for (int k0 = 0; k0 < IN_FEAT; k0 += BK) {
        float4 a4 = make_float4(0.f, 0.f, 0.f, 0.f);
        if (rowBase + aRow < M)
            a4 = *(const float4*)(Ab + (size_t)aRow * IN_FEAT + k0 + aCol);
        As2[aCol + 0][2 * aRow] = a4.x;  As2[aCol + 0][2 * aRow + 1] = a4.x;
        As2[aCol + 1][2 * aRow] = a4.y;  As2[aCol + 1][2 * aRow + 1] = a4.y;
        As2[aCol + 2][2 * aRow] = a4.z;  As2[aCol + 2][2 * aRow + 1] = a4.z;
        As2[aCol + 3][2 * aRow] = a4.w;  As2[aCol + 3][2 * aRow + 1] = a4.w;
        *(float4*)&Bs[bRow][bCol] =
            *(const float4*)(Bb + (size_t)(k0 + bRow) * NB + bCol);
        __syncthreads();

#pragma unroll
        for (int k = 0; k < BK; k++) {
            unsigned long long rM[TM];
            unsigned long long rN[4];
#pragma unroll
            for (int i = 0; i < TM; i++)
                rM[i] = *(const unsigned long long*)&As2[k][2 * (threadRow + i)];
#pragma unroll
            for (int p = 0; p < 4; p++)
                rN[p] = *(const unsigned long long*)&Bs[k][pairCol + 32 * p];
#pragma unroll
            for (int i = 0; i < TM; i++)
#pragma unroll
                for (int p = 0; p < 4; p++)
                    fma2(acc[i][p], rM[i], rN[p]);
        }
        __syncthreads();
    }

    // epilogue: 4 float2 stores per row (warp: lanes 0..15 contiguous 128B)
    float* Yb = g_Y + (size_t)rowBase * NB + cCol * BN;
#pragma unroll
    for (int i = 0; i < TM; i++) {
        if (rowBase + threadRow + i < M) {
            float* dst = Yb + (size_t)(threadRow + i) * NB;
#pragma unroll
            for (int p = 0; p < 4; p++) {
                float lo, hi;
                asm("mov.b64 {%0,%1}, %2;" : "=f"(lo), "=f"(hi) : "l"(acc[i][p]));
                *(float2*)(dst + pairCol + 32 * p) = make_float2(lo, hi);
            }
        }
    }
}

// ---------------------------------------------------------------------------
// Kernel 4: recombination  H[n, r*128+o] = sum_b w_comp[r,b] * Y[n, b*128+o]
// 256 threads = 2 nodes per CTA; fully coalesced reads/writes; memory-bound.
// ---------------------------------------------------------------------------
__global__ __launch_bounds__(256) void recomb_kernel(const float* __restrict__ w_comp,
                                                     int M)
{
    __shared__ float wc[NUM_RELS * NUM_BASES];   // 128 floats
    if (threadIdx.x < NUM_RELS * NUM_BASES)
        wc[threadIdx.x] = w_comp[threadIdx.x];
    __syncthreads();

    int node = blockIdx.x * 2 + (threadIdx.x >> 7);
    int o = threadIdx.x & 127;
    if (node >= M) return;

    const float* y = g_Y + (size_t)node * NB + o;
    float yv[NUM_BASES];
#pragma unroll
    for (int b = 0; b < NUM_BASES; b++)
        yv[b] = y[b * OUT_FEAT];

    float* h = g_H + (size_t)node * NCOL + o;
#pragma unroll
    for (int r = 0; r < NUM_RELS; r++) {
        float s = 0.f;
#pragma unroll
        for (int b = 0; b < NUM_BASES; b++)
            s += wc[r * NUM_BASES + b] * yv[b];
        h[r * OUT_FEAT] = s;
    }
}

// ---------------------------------------------------------------------------
// Kernel 5: out[n, :] = bias
// ---------------------------------------------------------------------------
__global__ void init_out_kernel(float* __restrict__ out,
                                const float* __restrict__ bias, int n_nodes)
{
    __shared__ float4 b4[OUT_FEAT / 4];
    if (threadIdx.x < OUT_FEAT / 4)
        b4[threadIdx.x] = ((const float4*)bias)[threadIdx.x];
    __syncthreads();
    size_t total = (size_t)n_nodes * (OUT_FEAT / 4);
    for (size_t i = (size_t)blockIdx.x * blockDim.x + threadIdx.x; i < total;
         i += (size_t)gridDim.x * blockDim.x)
        ((float4*)out)[i] = b4[i & (OUT_FEAT / 4 - 1)];
}

// ---------------------------------------------------------------------------
// Kernel 6: warp-per-edge gather + vectorized atomic scatter
// ---------------------------------------------------------------------------
__global__ __launch_bounds__(256) void edge_scatter_kernel(
    const void* __restrict__ srcp, const void* __restrict__ dstp,
    const void* __restrict__ etp, float* __restrict__ out, int n_edges)
{
    int gw = (blockIdx.x * 256 + threadIdx.x) >> 5;
    if (gw >= n_edges) return;
    int lane = threadIdx.x & 31;

    int s, d, t;
    if (g_idx64) {
        s = (int)((const long long*)srcp)[gw];
        d = (int)((const long long*)dstp)[gw];
        t = (int)((const long long*)etp)[gw];
    } else {
        s = ((const int*)srcp)[gw];
        d = ((const int*)dstp)[gw];
        t = ((const int*)etp)[gw];
    }

    const float4 v = __ldg(
        (const float4*)(g_H + ((size_t)s * NUM_RELS + t) * OUT_FEAT) + lane);
    float* o = out + (size_t)d * OUT_FEAT + lane * 4;
    asm volatile("red.global.add.v4.f32 [%0], {%1,%2,%3,%4};"
                 :: "l"(o), "f"(v.x), "f"(v.y), "f"(v.z), "f"(v.w) : "memory");
}

// ---------------------------------------------------------------------------
// launch.  Inputs: 0:x 1:weight 2:w_comp 3:h_bias 4:src 5:dst 6:etypes
// ---------------------------------------------------------------------------
extern "C" void kernel_launch(void* const* d_in, const int* in_sizes, int n_in,
                              void* d_out, int out_size)
{
    const float* x      = (const float*)d_in[0];
    const float* weight = (const float*)d_in[1];
    const float* w_comp = (const float*)d_in[2];
    const float* bias   = (const float*)d_in[3];
    const void*  src    = d_in[4];
    const void*  dst    = d_in[5];
    const void*  et     = d_in[6];
    float* out          = (float*)d_out;

    int n_nodes = in_sizes[0] / IN_FEAT;
    int n_edges = in_sizes[4];

    detect_idx_kernel<<<1, 256>>>((const unsigned int*)src, n_edges);
    prep_Wbb_kernel<<<(IN_FEAT * NB + 255) / 256, 256>>>(weight);

    {
        dim3 grid(NB / BN, (n_nodes + BM - 1) / BM);   // 8 x 782
        sgemm_y_kernel<<<grid, 256>>>(x, n_nodes);
    }

    recomb_kernel<<<(n_nodes + 1) / 2, 256>>>(w_comp, n_nodes);

    init_out_kernel<<<1024, 256>>>(out, bias, n_nodes);

    {
        int blocks = (n_edges + 7) / 8;   // 8 warps (edges) per CTA
        edge_scatter_kernel<<<blocks, 256>>>(src, dst, et, out, n_edges);
    }
}

// round 5
// speedup vs baseline: 1.6709x; 1.0922x over previous
#include <cuda_runtime.h>
#include <cuda_fp16.h>
#include <cstdint>

// ---------------------------------------------------------------------------
// RGCN layer, basis-factored, fp16 intermediates (fp32 accumulation everywhere):
//   y[n,b,o]  = sum_i x[n,i] * weight[b,i,o]      GEMM 100k x 1024, K=128 (fp32 math, fp16 store)
//   H[n,r,o]  = sum_b w_comp[r,b] * y[n,b,o]      memory-bound recombination (fp16 store)
//   out[d]    = bias + sum_{e: dst=d} H[src[e], etype[e], :]   (fp32 atomics)
// ---------------------------------------------------------------------------

#define MAX_NODES 100000
#define IN_FEAT   128
#define OUT_FEAT  128
#define NUM_RELS  16
#define NUM_BASES 8
#define NCOL      (NUM_RELS * OUT_FEAT)    // 2048
#define NB        (NUM_BASES * OUT_FEAT)   // 1024

// Scratch (static __device__ globals: allocation-free rule)
__device__ float  g_Wbb[IN_FEAT * NB];                 // B matrix [128][1024] (k-major)
__device__ __half g_Y[(size_t)MAX_NODES * NB];         // 204.8 MB
__device__ __half g_H[(size_t)MAX_NODES * NCOL];       // 409.6 MB
__device__ int    g_idx64;                             // 1 if index arrays are int64

// ---------------------------------------------------------------------------
// Kernel 1: detect whether index arrays are int64 or int32.
// ---------------------------------------------------------------------------
__global__ void detect_idx_kernel(const unsigned int* __restrict__ srcw, int n_edges)
{
    __shared__ int nz;
    if (threadIdx.x == 0) nz = 0;
    __syncthreads();
    int samples = n_edges < 2048 ? n_edges : 2048;
    for (int i = threadIdx.x; i < samples; i += blockDim.x)
        if (srcw[2 * i + 1] != 0u) atomicOr(&nz, 1);
    __syncthreads();
    if (threadIdx.x == 0) g_idx64 = (nz == 0) ? 1 : 0;
}

// ---------------------------------------------------------------------------
// Kernel 2: transpose-pack basis weights: Wbb[k][b*128+o] = weight[b,k,o]
// ---------------------------------------------------------------------------
__global__ void prep_Wbb_kernel(const float* __restrict__ weight)
{
    int idx = blockIdx.x * blockDim.x + threadIdx.x;
    if (idx >= IN_FEAT * NB) return;
    int k = idx >> 10;          // 0..127
    int n = idx & (NB - 1);     // 0..1023
    int b = n >> 7;
    int o = n & 127;
    g_Wbb[idx] = weight[((b * IN_FEAT) + k) * OUT_FEAT + o];
}

// ---------------------------------------------------------------------------
// Kernel 3: fp32 GEMM via packed fma.rn.f32x2, fp16 (half2) output.
//   Y[M x 1024] = A[M x 128] * Wbb[128 x 1024]
// BM=128, BN=128, BK=8, thread tile 8x8, 256 threads.
// A replicated in SMEM ({m,m} pairs -> broadcast LDS.64); thread columns are
// 4 pairs at stride 32 so rN LDS.64 across lanes 0..15 is conflict-free.
// ---------------------------------------------------------------------------
#define BM 128
#define BN 128
#define BK 8
#define TM 8

__device__ __forceinline__ void fma2(unsigned long long& d,
                                     unsigned long long a,
                                     unsigned long long b)
{
    asm("fma.rn.f32x2 %0, %1, %2, %0;" : "+l"(d) : "l"(a), "l"(b));
}

__global__ __launch_bounds__(256, 2) void sgemm_y_kernel(
    const float* __restrict__ A,   // x: M x 128
    int M)
{
    __shared__ float As2[BK][2 * BM];  // replicated A, 8 KB
    __shared__ float Bs[BK][BN];       // 4 KB

    const int tid  = threadIdx.x;
    const int cCol = blockIdx.x;            // 0..7
    const int rowBase = blockIdx.y * BM;

    const int aRow = tid >> 1;              // 0..127
    const int aCol = (tid & 1) * 4;         // 0 or 4
    const int bRow = tid >> 5;              // 0..7
    const int bCol = (tid & 31) * 4;        // 0..124

    const int threadRow = (tid >> 4) * TM;  // 0..120
    const int pairCol   = 2 * (tid & 15);   // 0..30  (pair p lives at pairCol + 32p)

    const float* Ab = A + (size_t)rowBase * IN_FEAT;
    const float* Bb = g_Wbb + cCol * BN;

    unsigned long long acc[TM][4];
#pragma unroll
    for (int i = 0; i < TM; i++)
#pragma unroll
        for (int p = 0; p < 4; p++) acc[i][p] = 0ull;

    for (int k0 = 0; k0 < IN_FEAT; k0 += BK) {
        float4 a4 = make_float4(0.f, 0.f, 0.f, 0.f);
        if (rowBase + aRow < M)
            a4 = *(const float4*)(Ab + (size_t)aRow * IN_FEAT + k0 + aCol);
        As2[aCol + 0][2 * aRow] = a4.x;  As2[aCol + 0][2 * aRow + 1] = a4.x;
        As2[aCol + 1][2 * aRow] = a4.y;  As2[aCol + 1][2 * aRow + 1] = a4.y;
        As2[aCol + 2][2 * aRow] = a4.z;  As2[aCol + 2][2 * aRow + 1] = a4.z;
        As2[aCol + 3][2 * aRow] = a4.w;  As2[aCol + 3][2 * aRow + 1] = a4.w;
        *(float4*)&Bs[bRow][bCol] =
            *(const float4*)(Bb + (size_t)(k0 + bRow) * NB + bCol);
        __syncthreads();

#pragma unroll
        for (int k = 0; k < BK; k++) {
            unsigned long long rM[TM];
            unsigned long long rN[4];
#pragma unroll
            for (int i = 0; i < TM; i++)
                rM[i] = *(const unsigned long long*)&As2[k][2 * (threadRow + i)];
#pragma unroll
            for (int p = 0; p < 4; p++)
                rN[p] = *(const unsigned long long*)&Bs[k][pairCol + 32 * p];
#pragma unroll
            for (int i = 0; i < TM; i++)
#pragma unroll
                for (int p = 0; p < 4; p++)
                    fma2(acc[i][p], rM[i], rN[p]);
        }
        __syncthreads();
    }

    // epilogue: half2 stores (lanes 0..15 contiguous 64B per pair-group)
    __half* Yb = g_Y + (size_t)rowBase * NB + cCol * BN;
#pragma unroll
    for (int i = 0; i < TM; i++) {
        if (rowBase + threadRow + i < M) {
            __half* dst = Yb + (size_t)(threadRow + i) * NB;
#pragma unroll
            for (int p = 0; p < 4; p++) {
                float lo, hi;
                asm("mov.b64 {%0,%1}, %2;" : "=f"(lo), "=f"(hi) : "l"(acc[i][p]));
                *(__half2*)(dst + pairCol + 32 * p) = __floats2half2_rn(lo, hi);
            }
        }
    }
}

// ---------------------------------------------------------------------------
// Kernel 4: recombination  H[n, r*128+o] = sum_b w_comp[r,b] * Y[n, b*128+o]
// 256 threads = 2 nodes per CTA; coalesced (64B per warp-transaction).
// ---------------------------------------------------------------------------
__global__ __launch_bounds__(256) void recomb_kernel(const float* __restrict__ w_comp,
                                                     int M)
{
    __shared__ float wc[NUM_RELS * NUM_BASES];   // 128 floats
    if (threadIdx.x < NUM_RELS * NUM_BASES)
        wc[threadIdx.x] = w_comp[threadIdx.x];
    __syncthreads();

    int node = blockIdx.x * 2 + (threadIdx.x >> 7);
    int o = threadIdx.x & 127;
    if (node >= M) return;

    const __half* y = g_Y + (size_t)node * NB + o;
    float yv[NUM_BASES];
#pragma unroll
    for (int b = 0; b < NUM_BASES; b++)
        yv[b] = __half2float(y[b * OUT_FEAT]);

    __half* h = g_H + (size_t)node * NCOL + o;
#pragma unroll
    for (int r = 0; r < NUM_RELS; r++) {
        float s = 0.f;
#pragma unroll
        for (int b = 0; b < NUM_BASES; b++)
            s += wc[r * NUM_BASES + b] * yv[b];
        h[r * OUT_FEAT] = __float2half_rn(s);
    }
}

// ---------------------------------------------------------------------------
// Kernel 5: out[n, :] = bias
// ---------------------------------------------------------------------------
__global__ void init_out_kernel(float* __restrict__ out,
                                const float* __restrict__ bias, int n_nodes)
{
    __shared__ float4 b4[OUT_FEAT / 4];
    if (threadIdx.x < OUT_FEAT / 4)
        b4[threadIdx.x] = ((const float4*)bias)[threadIdx.x];
    __syncthreads();
    size_t total = (size_t)n_nodes * (OUT_FEAT / 4);
    for (size_t i = (size_t)blockIdx.x * blockDim.x + threadIdx.x; i < total;
         i += (size_t)gridDim.x * blockDim.x)
        ((float4*)out)[i] = b4[i & (OUT_FEAT / 4 - 1)];
}

// ---------------------------------------------------------------------------
// Kernel 6: half-warp-per-edge gather (fp16, 256B/edge) + fp32 vector atomics
// ---------------------------------------------------------------------------
__global__ __launch_bounds__(256) void edge_scatter_kernel(
    const void* __restrict__ srcp, const void* __restrict__ dstp,
    const void* __restrict__ etp, float* __restrict__ out, int n_edges)
{
    int warp = (blockIdx.x * 256 + threadIdx.x) >> 5;
    int lane = threadIdx.x & 31;
    int e = warp * 2 + (lane >> 4);       // edge id for this half-warp
    int hl = lane & 15;
    if (e >= n_edges) return;

    int s, d, t;
    if (g_idx64) {
        s = (int)((const long long*)srcp)[e];
        d = (int)((const long long*)dstp)[e];
        t = (int)((const long long*)etp)[e];
    } else {
        s = ((const int*)srcp)[e];
        d = ((const int*)dstp)[e];
        t = ((const int*)etp)[e];
    }

    // 16 lanes x 16B = full 256B fp16 message
    const uint4 v = __ldg(
        (const uint4*)(g_H + ((size_t)s * NUM_RELS + t) * OUT_FEAT) + hl);
    float2 f0 = __half22float2(*(const __half2*)&v.x);
    float2 f1 = __half22float2(*(const __half2*)&v.y);
    float2 f2 = __half22float2(*(const __half2*)&v.z);
    float2 f3 = __half22float2(*(const __half2*)&v.w);

    float* o = out + (size_t)d * OUT_FEAT + hl * 8;
    asm volatile("red.global.add.v4.f32 [%0], {%1,%2,%3,%4};"
                 :: "l"(o), "f"(f0.x), "f"(f0.y), "f"(f1.x), "f"(f1.y) : "memory");
    asm volatile("red.global.add.v4.f32 [%0], {%1,%2,%3,%4};"
                 :: "l"(o + 4), "f"(f2.x), "f"(f2.y), "f"(f3.x), "f"(f3.y) : "memory");
}

// ---------------------------------------------------------------------------
// launch.  Inputs: 0:x 1:weight 2:w_comp 3:h_bias 4:src 5:dst 6:etypes
// ---------------------------------------------------------------------------
extern "C" void kernel_launch(void* const* d_in, const int* in_sizes, int n_in,
                              void* d_out, int out_size)
{
    const float* x      = (const float*)d_in[0];
    const float* weight = (const float*)d_in[1];
    const float* w_comp = (const float*)d_in[2];
    const float* bias   = (const float*)d_in[3];
    const void*  src    = d_in[4];
    const void*  dst    = d_in[5];
    const void*  et     = d_in[6];
    float* out          = (float*)d_out;

    int n_nodes = in_sizes[0] / IN_FEAT;
    int n_edges = in_sizes[4];

    detect_idx_kernel<<<1, 256>>>((const unsigned int*)src, n_edges);
    prep_Wbb_kernel<<<(IN_FEAT * NB + 255) / 256, 256>>>(weight);

    {
        dim3 grid(NB / BN, (n_nodes + BM - 1) / BM);   // 8 x 782
        sgemm_y_kernel<<<grid, 256>>>(x, n_nodes);
    }

    recomb_kernel<<<(n_nodes + 1) / 2, 256>>>(w_comp, n_nodes);

    init_out_kernel<<<1024, 256>>>(out, bias, n_nodes);

    {
        // 2 edges per warp, 8 warps per CTA -> 16 edges per CTA
        int blocks = (n_edges + 15) / 16;
        edge_scatter_kernel<<<blocks, 256>>>(src, dst, et, out, n_edges);
    }
}

// round 6
// speedup vs baseline: 1.9865x; 1.1889x over previous
#include <cuda_runtime.h>
#include <cuda_fp16.h>
#include <cstdint>

// ---------------------------------------------------------------------------
// RGCN layer, basis-factored, fp16 intermediates, CSR-aggregated epilogue:
//   y[n,b,o]  = sum_i x[n,i] * weight[b,i,o]      GEMM (fp32 FFMA2, fp16 store)
//   H[n,r,o]  = sum_b w_comp[r,b] * y[n,b,o]      half2 recombination
//   CSR by dst, then warp-per-node:  out[d] = bias + sum_{e in csr[d]} H[src_e, et_e]
// ---------------------------------------------------------------------------

#define MAX_NODES 100000
#define MAX_EDGES 3200000
#define IN_FEAT   128
#define OUT_FEAT  128
#define NUM_RELS  16
#define NUM_BASES 8
#define NCOL      (NUM_RELS * OUT_FEAT)    // 2048
#define NB        (NUM_BASES * OUT_FEAT)   // 1024

// Scratch (static __device__ globals: allocation-free rule)
__device__ float    g_Wbb[IN_FEAT * NB];               // [128][1024] k-major
__device__ __half   g_Y[(size_t)MAX_NODES * NB];       // 204.8 MB
__device__ __half   g_H[(size_t)MAX_NODES * NCOL];     // 409.6 MB
__device__ int      g_off[MAX_NODES + 1];              // CSR offsets (also deg scratch)
__device__ int      g_cursor[MAX_NODES];               // fill cursors
__device__ unsigned g_einfo[MAX_EDGES];                // src | (etype<<20), dst-sorted
__device__ int      g_idx64;                           // 1 if index arrays are int64

// ---------------------------------------------------------------------------
// Kernel 1: detect index dtype (int64 vs int32)
// ---------------------------------------------------------------------------
__global__ void detect_idx_kernel(const unsigned int* __restrict__ srcw, int n_edges)
{
    __shared__ int nz;
    if (threadIdx.x == 0) nz = 0;
    __syncthreads();
    int samples = n_edges < 2048 ? n_edges : 2048;
    for (int i = threadIdx.x; i < samples; i += blockDim.x)
        if (srcw[2 * i + 1] != 0u) atomicOr(&nz, 1);
    __syncthreads();
    if (threadIdx.x == 0) g_idx64 = (nz == 0) ? 1 : 0;
}

// ---------------------------------------------------------------------------
// Kernel 2: transpose-pack basis weights: Wbb[k][b*128+o] = weight[b,k,o]
// ---------------------------------------------------------------------------
__global__ void prep_Wbb_kernel(const float* __restrict__ weight)
{
    int idx = blockIdx.x * blockDim.x + threadIdx.x;
    if (idx >= IN_FEAT * NB) return;
    int k = idx >> 10;
    int n = idx & (NB - 1);
    int b = n >> 7;
    int o = n & 127;
    g_Wbb[idx] = weight[((b * IN_FEAT) + k) * OUT_FEAT + o];
}

// ---------------------------------------------------------------------------
// Kernel 3: fp32 GEMM via packed fma.rn.f32x2, fp16 output.
// ---------------------------------------------------------------------------
#define BM 128
#define BN 128
#define BK 8
#define TM 8

__device__ __forceinline__ void fma2(unsigned long long& d,
                                     unsigned long long a,
                                     unsigned long long b)
{
    asm("fma.rn.f32x2 %0, %1, %2, %0;" : "+l"(d) : "l"(a), "l"(b));
}

__global__ __launch_bounds__(256, 2) void sgemm_y_kernel(
    const float* __restrict__ A, int M)
{
    __shared__ float As2[BK][2 * BM];
    __shared__ float Bs[BK][BN];

    const int tid  = threadIdx.x;
    const int cCol = blockIdx.x;
    const int rowBase = blockIdx.y * BM;

    const int aRow = tid >> 1;
    const int aCol = (tid & 1) * 4;
    const int bRow = tid >> 5;
    const int bCol = (tid & 31) * 4;

    const int threadRow = (tid >> 4) * TM;
    const int pairCol   = 2 * (tid & 15);

    const float* Ab = A + (size_t)rowBase * IN_FEAT;
    const float* Bb = g_Wbb + cCol * BN;

    unsigned long long acc[TM][4];
#pragma unroll
    for (int i = 0; i < TM; i++)
#pragma unroll
        for (int p = 0; p < 4; p++) acc[i][p] = 0ull;

    for (int k0 = 0; k0 < IN_FEAT; k0 += BK) {
        float4 a4 = make_float4(0.f, 0.f, 0.f, 0.f);
        if (rowBase + aRow < M)
            a4 = *(const float4*)(Ab + (size_t)aRow * IN_FEAT + k0 + aCol);
        As2[aCol + 0][2 * aRow] = a4.x;  As2[aCol + 0][2 * aRow + 1] = a4.x;
        As2[aCol + 1][2 * aRow] = a4.y;  As2[aCol + 1][2 * aRow + 1] = a4.y;
        As2[aCol + 2][2 * aRow] = a4.z;  As2[aCol + 2][2 * aRow + 1] = a4.z;
        As2[aCol + 3][2 * aRow] = a4.w;  As2[aCol + 3][2 * aRow + 1] = a4.w;
        *(float4*)&Bs[bRow][bCol] =
            *(const float4*)(Bb + (size_t)(k0 + bRow) * NB + bCol);
        __syncthreads();

#pragma unroll
        for (int k = 0; k < BK; k++) {
            unsigned long long rM[TM];
            unsigned long long rN[4];
#pragma unroll
            for (int i = 0; i < TM; i++)
                rM[i] = *(const unsigned long long*)&As2[k][2 * (threadRow + i)];
#pragma unroll
            for (int p = 0; p < 4; p++)
                rN[p] = *(const unsigned long long*)&Bs[k][pairCol + 32 * p];
#pragma unroll
            for (int i = 0; i < TM; i++)
#pragma unroll
                for (int p = 0; p < 4; p++)
                    fma2(acc[i][p], rM[i], rN[p]);
        }
        __syncthreads();
    }

    __half* Yb = g_Y + (size_t)rowBase * NB + cCol * BN;
#pragma unroll
    for (int i = 0; i < TM; i++) {
        if (rowBase + threadRow + i < M) {
            __half* dst = Yb + (size_t)(threadRow + i) * NB;
#pragma unroll
            for (int p = 0; p < 4; p++) {
                float lo, hi;
                asm("mov.b64 {%0,%1}, %2;" : "=f"(lo), "=f"(hi) : "l"(acc[i][p]));
                *(__half2*)(dst + pairCol + 32 * p) = __floats2half2_rn(lo, hi);
            }
        }
    }
}

// ---------------------------------------------------------------------------
// Kernel 4: half2 recombination  H[n, r, o2] = sum_b wc[r,b] * Y[n, b, o2]
// 256 threads = 4 nodes/CTA; 128B/warp transactions.
// ---------------------------------------------------------------------------
__global__ __launch_bounds__(256) void recomb_kernel(const float* __restrict__ w_comp,
                                                     int M)
{
    __shared__ float wc[NUM_RELS * NUM_BASES];
    if (threadIdx.x < NUM_RELS * NUM_BASES)
        wc[threadIdx.x] = w_comp[threadIdx.x];
    __syncthreads();

    int node = blockIdx.x * 4 + (threadIdx.x >> 6);
    int op   = threadIdx.x & 63;            // half2 column pair
    if (node >= M) return;

    const __half2* y = (const __half2*)(g_Y + (size_t)node * NB) + op;
    float2 yv[NUM_BASES];
#pragma unroll
    for (int b = 0; b < NUM_BASES; b++)
        yv[b] = __half22float2(y[b * 64]);

    __half2* h = (__half2*)(g_H + (size_t)node * NCOL) + op;
#pragma unroll
    for (int r = 0; r < NUM_RELS; r++) {
        float sx = 0.f, sy = 0.f;
#pragma unroll
        for (int b = 0; b < NUM_BASES; b++) {
            float w = wc[r * NUM_BASES + b];
            sx += w * yv[b].x;
            sy += w * yv[b].y;
        }
        h[r * 64] = __floats2half2_rn(sx, sy);
    }
}

// ---------------------------------------------------------------------------
// CSR build: zero -> histogram -> single-CTA chunked scan -> fill
// ---------------------------------------------------------------------------
__global__ void zero_deg_kernel(int n_nodes)
{
    for (int i = blockIdx.x * blockDim.x + threadIdx.x; i <= n_nodes;
         i += gridDim.x * blockDim.x)
        g_off[i] = 0;
}

__global__ void hist_kernel(const void* __restrict__ dstp, int n_edges)
{
    for (int e = blockIdx.x * blockDim.x + threadIdx.x; e < n_edges;
         e += gridDim.x * blockDim.x) {
        int d = g_idx64 ? (int)((const long long*)dstp)[e] : ((const int*)dstp)[e];
        atomicAdd(&g_off[d], 1);
    }
}

__global__ __launch_bounds__(1024) void scan_kernel(int n_nodes)
{
    __shared__ int ps[1024];
    const int t = threadIdx.x;
    const int C = (n_nodes + 1023) / 1024;
    const int beg = t * C;
    const int end = min(beg + C, n_nodes);

    int sum = 0;
    for (int i = beg; i < end; i++) sum += g_off[i];
    ps[t] = sum;
    __syncthreads();

    // inclusive Hillis-Steele scan over 1024 partials
    for (int s = 1; s < 1024; s <<= 1) {
        int v = (t >= s) ? ps[t - s] : 0;
        __syncthreads();
        ps[t] += v;
        __syncthreads();
    }

    int run = (t == 0) ? 0 : ps[t - 1];
    for (int i = beg; i < end; i++) {
        int dgi = g_off[i];           // read deg before overwrite (in-place safe)
        g_off[i] = run;
        g_cursor[i] = run;
        run += dgi;
    }
    if (t == 0) g_off[n_nodes] = ps[1023];
}

__global__ void fill_kernel(const void* __restrict__ srcp,
                            const void* __restrict__ dstp,
                            const void* __restrict__ etp, int n_edges)
{
    for (int e = blockIdx.x * blockDim.x + threadIdx.x; e < n_edges;
         e += gridDim.x * blockDim.x) {
        int s, d, t;
        if (g_idx64) {
            s = (int)((const long long*)srcp)[e];
            d = (int)((const long long*)dstp)[e];
            t = (int)((const long long*)etp)[e];
        } else {
            s = ((const int*)srcp)[e];
            d = ((const int*)dstp)[e];
            t = ((const int*)etp)[e];
        }
        int p = atomicAdd(&g_cursor[d], 1);
        g_einfo[p] = (unsigned)s | ((unsigned)t << 20);
    }
}

// ---------------------------------------------------------------------------
// Kernel 5: warp-per-destination aggregation (no atomics).
//   out[d, :] = bias + sum_{e in csr[d]} H[src_e*16 + et_e, :]
// Each lane owns 4 output columns; per edge a warp reads 256B coalesced.
// ---------------------------------------------------------------------------
__global__ __launch_bounds__(256) void aggregate_kernel(
    const float* __restrict__ bias, float* __restrict__ out, int M)
{
    int node = (blockIdx.x * 256 + threadIdx.x) >> 5;
    int lane = threadIdx.x & 31;
    if (node >= M) return;

    const int beg = g_off[node];
    const int end = g_off[node + 1];

    float a0 = 0.f, a1 = 0.f, a2 = 0.f, a3 = 0.f;
    for (int i = beg; i < end; i++) {
        unsigned ei = __ldg(&g_einfo[i]);
        unsigned s = ei & 0xFFFFFu;
        unsigned t = ei >> 20;
        const uint2 v = __ldg(
            (const uint2*)(g_H + ((size_t)s * NUM_RELS + t) * OUT_FEAT) + lane);
        float2 f0 = __half22float2(*(const __half2*)&v.x);
        float2 f1 = __half22float2(*(const __half2*)&v.y);
        a0 += f0.x; a1 += f0.y; a2 += f1.x; a3 += f1.y;
    }

    const float4 bv = __ldg((const float4*)bias + lane);
    *(float4*)(out + (size_t)node * OUT_FEAT + lane * 4) =
        make_float4(a0 + bv.x, a1 + bv.y, a2 + bv.z, a3 + bv.w);
}

// ---------------------------------------------------------------------------
// launch.  Inputs: 0:x 1:weight 2:w_comp 3:h_bias 4:src 5:dst 6:etypes
// ---------------------------------------------------------------------------
extern "C" void kernel_launch(void* const* d_in, const int* in_sizes, int n_in,
                              void* d_out, int out_size)
{
    const float* x      = (const float*)d_in[0];
    const float* weight = (const float*)d_in[1];
    const float* w_comp = (const float*)d_in[2];
    const float* bias   = (const float*)d_in[3];
    const void*  src    = d_in[4];
    const void*  dst    = d_in[5];
    const void*  et     = d_in[6];
    float* out          = (float*)d_out;

    int n_nodes = in_sizes[0] / IN_FEAT;
    int n_edges = in_sizes[4];

    detect_idx_kernel<<<1, 256>>>((const unsigned int*)src, n_edges);
    prep_Wbb_kernel<<<(IN_FEAT * NB + 255) / 256, 256>>>(weight);

    // GEMM  Y = x @ Wbb
    {
        dim3 grid(NB / BN, (n_nodes + BM - 1) / BM);
        sgemm_y_kernel<<<grid, 256>>>(x, n_nodes);
    }

    // CSR build (overlaps GEMM-adjacent stream; cheap)
    zero_deg_kernel<<<128, 256>>>(n_nodes);
    hist_kernel<<<2048, 256>>>(dst, n_edges);
    scan_kernel<<<1, 1024>>>(n_nodes);
    fill_kernel<<<2048, 256>>>(src, dst, et, n_edges);

    // H = recombine(Y)
    recomb_kernel<<<(n_nodes + 3) / 4, 256>>>(w_comp, n_nodes);

    // out = bias + CSR-aggregated messages
    aggregate_kernel<<<(n_nodes * 32 + 255) / 256, 256>>>(bias, out, n_nodes);
}

// round 7
// speedup vs baseline: 2.9115x; 1.4656x over previous
#include <cuda_runtime.h>
#include <cuda_fp16.h>
#include <cstdint>

// ---------------------------------------------------------------------------
// RGCN layer, basis-factored, fp16 intermediates, tensor-core GEMM:
//   y[n,b,o]  = sum_i x[n,i] * weight[b,i,o]   mma.sync fp16, A split hi/lo (2-term)
//   H[n,r,o]  = sum_b w_comp[r,b] * y[n,b,o]   half2 recombination
//   CSR by dst, warp-per-node:  out[d] = bias + sum_{e in csr[d]} H[src_e, et_e]
// ---------------------------------------------------------------------------

#define MAX_NODES 100000
#define MAX_EDGES 3200000
#define IN_FEAT   128
#define OUT_FEAT  128
#define NUM_RELS  16
#define NUM_BASES 8
#define NCOL      (NUM_RELS * OUT_FEAT)    // 2048
#define NB        (NUM_BASES * OUT_FEAT)   // 1024

// Scratch (static __device__ globals: allocation-free rule)
__device__ __half   g_WbT[NB * IN_FEAT];               // B^T [n][k] fp16, 256 KB
__device__ __half   g_Y[(size_t)MAX_NODES * NB];       // 204.8 MB
__device__ __half   g_H[(size_t)MAX_NODES * NCOL];     // 409.6 MB
__device__ int      g_off[MAX_NODES + 1];              // CSR offsets
__device__ int      g_cursor[MAX_NODES];
__device__ unsigned g_einfo[MAX_EDGES];                // src | (etype<<20)
__device__ int      g_idx64;

// ---------------------------------------------------------------------------
// Kernel 1: detect index dtype (int64 vs int32)
// ---------------------------------------------------------------------------
__global__ void detect_idx_kernel(const unsigned int* __restrict__ srcw, int n_edges)
{
    __shared__ int nz;
    if (threadIdx.x == 0) nz = 0;
    __syncthreads();
    int samples = n_edges < 2048 ? n_edges : 2048;
    for (int i = threadIdx.x; i < samples; i += blockDim.x)
        if (srcw[2 * i + 1] != 0u) atomicOr(&nz, 1);
    __syncthreads();
    if (threadIdx.x == 0) g_idx64 = (nz == 0) ? 1 : 0;
}

// ---------------------------------------------------------------------------
// Kernel 2: WbT[n=b*128+o][k] = (half)weight[b,k,o]
// ---------------------------------------------------------------------------
__global__ void prep_WbT_kernel(const float* __restrict__ weight)
{
    int idx = blockIdx.x * blockDim.x + threadIdx.x;
    if (idx >= NB * IN_FEAT) return;
    int n = idx >> 7;
    int k = idx & 127;
    int b = n >> 7;
    int o = n & 127;
    g_WbT[idx] = __float2half_rn(weight[((b * IN_FEAT) + k) * OUT_FEAT + o]);
}

// ---------------------------------------------------------------------------
// Kernel 3: tensor-core GEMM  Y[M x 1024] = x[M x 128] @ WbT^T
// mma.sync.m16n8k16.f32.f16.f16.f32 ; 2-term split on A (hi + residual).
// CTA tile 128x256, 8 warps (2m x 4n), warp tile 64x64, K=128 single shot.
// SMEM rows padded to 68 words: fragment LDS banks = 4*(lane>>2)+(lane&3),
// all 32 distinct -> conflict-free.
// ---------------------------------------------------------------------------
#define AST 68
#define BST 68
#define GM_SMEM_WORDS (2 * 128 * AST + 256 * BST)      // 34816
#define GM_SMEM_BYTES (GM_SMEM_WORDS * 4)              // 139264

__device__ __forceinline__ uint32_t pk(__half a, __half b)
{
    __half2 t = __halves2half2(a, b);
    return *(uint32_t*)&t;
}

__device__ __forceinline__ void mma16816(float* d, const uint32_t* a, const uint32_t* b)
{
    asm volatile(
        "mma.sync.aligned.m16n8k16.row.col.f32.f16.f16.f32 "
        "{%0,%1,%2,%3}, {%4,%5,%6,%7}, {%8,%9}, {%0,%1,%2,%3};"
        : "+f"(d[0]), "+f"(d[1]), "+f"(d[2]), "+f"(d[3])
        : "r"(a[0]), "r"(a[1]), "r"(a[2]), "r"(a[3]), "r"(b[0]), "r"(b[1]));
}

__global__ __launch_bounds__(256, 1) void hgemm_y_kernel(
    const float* __restrict__ A, int M)
{
    extern __shared__ uint32_t sh[];
    uint32_t* Ah = sh;
    uint32_t* Al = sh + 128 * AST;
    uint32_t* Bw = sh + 2 * 128 * AST;

    const int tid = threadIdx.x;
    const int rowBase = blockIdx.y * 128;
    const int colBase = blockIdx.x * 256;

    // --- load A tile (128x128 fp32), split to hi/lo fp16 ---
    {
        int r = tid >> 1;
        int kbase = (tid & 1) * 64;
        bool ok = (rowBase + r) < M;
        const float4* src = (const float4*)(A + (size_t)(rowBase + r) * IN_FEAT + kbase);
#pragma unroll
        for (int j = 0; j < 16; j++) {
            float4 v = make_float4(0.f, 0.f, 0.f, 0.f);
            if (ok) v = src[j];
            __half hx = __float2half_rn(v.x), hy = __float2half_rn(v.y);
            __half hz = __float2half_rn(v.z), hw = __float2half_rn(v.w);
            __half lx = __float2half_rn(v.x - __half2float(hx));
            __half ly = __float2half_rn(v.y - __half2float(hy));
            __half lz = __float2half_rn(v.z - __half2float(hz));
            __half lw = __float2half_rn(v.w - __half2float(hw));
            int w = r * AST + ((kbase + j * 4) >> 1);
            Ah[w]     = pk(hx, hy);
            Ah[w + 1] = pk(hz, hw);
            Al[w]     = pk(lx, ly);
            Al[w + 1] = pk(lz, lw);
        }
    }
    // --- load B tile (256 n-rows x 128 k fp16) ---
    {
        const uint4* src = (const uint4*)(g_WbT + (size_t)(colBase + tid) * IN_FEAT);
#pragma unroll
        for (int j = 0; j < 16; j++)
            *(uint4*)(Bw + tid * BST + j * 4) = src[j];
    }
    __syncthreads();

    const int lane = tid & 31;
    const int warp = tid >> 5;
    const int wm = warp & 1;            // 0..1
    const int wn = warp >> 1;           // 0..3
    const int g  = lane >> 2;           // 0..7
    const int tg = lane & 3;            // 0..3

    float acc[4][8][4];
#pragma unroll
    for (int i = 0; i < 4; i++)
#pragma unroll
        for (int j = 0; j < 8; j++)
#pragma unroll
            for (int c = 0; c < 4; c++) acc[i][j][c] = 0.f;

#pragma unroll
    for (int ks = 0; ks < 8; ks++) {
        const int kw = ks * 8;
        uint32_t bf[8][2];
#pragma unroll
        for (int nA = 0; nA < 8; nA++) {
            int n = wn * 64 + nA * 8 + g;
            bf[nA][0] = Bw[n * BST + kw + tg];
            bf[nA][1] = Bw[n * BST + kw + 4 + tg];
        }
#pragma unroll
        for (int mA = 0; mA < 4; mA++) {
            int r = wm * 64 + mA * 16 + g;
            uint32_t ah[4], al[4];
            ah[0] = Ah[r * AST + kw + tg];
            ah[1] = Ah[(r + 8) * AST + kw + tg];
            ah[2] = Ah[r * AST + kw + 4 + tg];
            ah[3] = Ah[(r + 8) * AST + kw + 4 + tg];
            al[0] = Al[r * AST + kw + tg];
            al[1] = Al[(r + 8) * AST + kw + tg];
            al[2] = Al[r * AST + kw + 4 + tg];
            al[3] = Al[(r + 8) * AST + kw + 4 + tg];
#pragma unroll
            for (int nA = 0; nA < 8; nA++) {
                mma16816(acc[mA][nA], ah, bf[nA]);
                mma16816(acc[mA][nA], al, bf[nA]);
            }
        }
    }

    // --- epilogue: fp16 half2 stores into Y ---
    __half2* Yp = (__half2*)g_Y;
#pragma unroll
    for (int mA = 0; mA < 4; mA++) {
        int r0 = rowBase + wm * 64 + mA * 16 + g;
#pragma unroll
        for (int nA = 0; nA < 8; nA++) {
            int col = colBase + wn * 64 + nA * 8 + 2 * tg;
            if (r0 < M)
                Yp[(size_t)r0 * (NB / 2) + (col >> 1)] =
                    __floats2half2_rn(acc[mA][nA][0], acc[mA][nA][1]);
            if (r0 + 8 < M)
                Yp[(size_t)(r0 + 8) * (NB / 2) + (col >> 1)] =
                    __floats2half2_rn(acc[mA][nA][2], acc[mA][nA][3]);
        }
    }
}

// ---------------------------------------------------------------------------
// Kernel 4: half2 recombination  H[n, r, o2] = sum_b wc[r,b] * Y[n, b, o2]
// ---------------------------------------------------------------------------
__global__ __launch_bounds__(256) void recomb_kernel(const float* __restrict__ w_comp,
                                                     int M)
{
    __shared__ float wc[NUM_RELS * NUM_BASES];
    if (threadIdx.x < NUM_RELS * NUM_BASES)
        wc[threadIdx.x] = w_comp[threadIdx.x];
    __syncthreads();

    int node = blockIdx.x * 4 + (threadIdx.x >> 6);
    int op   = threadIdx.x & 63;
    if (node >= M) return;

    const __half2* y = (const __half2*)(g_Y + (size_t)node * NB) + op;
    float2 yv[NUM_BASES];
#pragma unroll
    for (int b = 0; b < NUM_BASES; b++)
        yv[b] = __half22float2(y[b * 64]);

    __half2* h = (__half2*)(g_H + (size_t)node * NCOL) + op;
#pragma unroll
    for (int r = 0; r < NUM_RELS; r++) {
        float sx = 0.f, sy = 0.f;
#pragma unroll
        for (int b = 0; b < NUM_BASES; b++) {
            float w = wc[r * NUM_BASES + b];
            sx += w * yv[b].x;
            sy += w * yv[b].y;
        }
        h[r * 64] = __floats2half2_rn(sx, sy);
    }
}

// ---------------------------------------------------------------------------
// CSR build: zero -> histogram -> single-CTA chunked scan -> fill
// ---------------------------------------------------------------------------
__global__ void zero_deg_kernel(int n_nodes)
{
    for (int i = blockIdx.x * blockDim.x + threadIdx.x; i <= n_nodes;
         i += gridDim.x * blockDim.x)
        g_off[i] = 0;
}

__global__ void hist_kernel(const void* __restrict__ dstp, int n_edges)
{
    for (int e = blockIdx.x * blockDim.x + threadIdx.x; e < n_edges;
         e += gridDim.x * blockDim.x) {
        int d = g_idx64 ? (int)((const long long*)dstp)[e] : ((const int*)dstp)[e];
        atomicAdd(&g_off[d], 1);
    }
}

__global__ __launch_bounds__(1024) void scan_kernel(int n_nodes)
{
    __shared__ int ps[1024];
    const int t = threadIdx.x;
    const int C = (n_nodes + 1023) / 1024;
    const int beg = t * C;
    const int end = min(beg + C, n_nodes);

    int sum = 0;
    for (int i = beg; i < end; i++) sum += g_off[i];
    ps[t] = sum;
    __syncthreads();

    for (int s = 1; s < 1024; s <<= 1) {
        int v = (t >= s) ? ps[t - s] : 0;
        __syncthreads();
        ps[t] += v;
        __syncthreads();
    }

    int run = (t == 0) ? 0 : ps[t - 1];
    for (int i = beg; i < end; i++) {
        int dgi = g_off[i];
        g_off[i] = run;
        g_cursor[i] = run;
        run += dgi;
    }
    if (t == 0) g_off[n_nodes] = ps[1023];
}

__global__ void fill_kernel(const void* __restrict__ srcp,
                            const void* __restrict__ dstp,
                            const void* __restrict__ etp, int n_edges)
{
    for (int e = blockIdx.x * blockDim.x + threadIdx.x; e < n_edges;
         e += gridDim.x * blockDim.x) {
        int s, d, t;
        if (g_idx64) {
            s = (int)((const long long*)srcp)[e];
            d = (int)((const long long*)dstp)[e];
            t = (int)((const long long*)etp)[e];
        } else {
            s = ((const int*)srcp)[e];
            d = ((const int*)dstp)[e];
            t = ((const int*)etp)[e];
        }
        int p = atomicAdd(&g_cursor[d], 1);
        g_einfo[p] = (unsigned)s | ((unsigned)t << 20);
    }
}

// ---------------------------------------------------------------------------
// Kernel 5: warp-per-destination aggregation, unrolled x4 for MLP.
// ---------------------------------------------------------------------------
__device__ __forceinline__ const uint2* hrow(unsigned ei, int lane)
{
    size_t off = ((size_t)(ei & 0xFFFFFu) * NUM_RELS + (ei >> 20)) * OUT_FEAT;
    return (const uint2*)(g_H + off) + lane;
}

__global__ __launch_bounds__(256) void aggregate_kernel(
    const float* __restrict__ bias, float* __restrict__ out, int M)
{
    int node = (blockIdx.x * 256 + threadIdx.x) >> 5;
    int lane = threadIdx.x & 31;
    if (node >= M) return;

    const int beg = g_off[node];
    const int end = g_off[node + 1];

    float a0 = 0.f, a1 = 0.f, a2 = 0.f, a3 = 0.f;
    int i = beg;
    for (; i + 4 <= end; i += 4) {
        unsigned e0 = __ldg(&g_einfo[i + 0]);
        unsigned e1 = __ldg(&g_einfo[i + 1]);
        unsigned e2 = __ldg(&g_einfo[i + 2]);
        unsigned e3 = __ldg(&g_einfo[i + 3]);
        uint2 v0 = __ldg(hrow(e0, lane));
        uint2 v1 = __ldg(hrow(e1, lane));
        uint2 v2 = __ldg(hrow(e2, lane));
        uint2 v3 = __ldg(hrow(e3, lane));
        float2 p;
        p = __half22float2(*(const __half2*)&v0.x); a0 += p.x; a1 += p.y;
        p = __half22float2(*(const __half2*)&v0.y); a2 += p.x; a3 += p.y;
        p = __half22float2(*(const __half2*)&v1.x); a0 += p.x; a1 += p.y;
        p = __half22float2(*(const __half2*)&v1.y); a2 += p.x; a3 += p.y;
        p = __half22float2(*(const __half2*)&v2.x); a0 += p.x; a1 += p.y;
        p = __half22float2(*(const __half2*)&v2.y); a2 += p.x; a3 += p.y;
        p = __half22float2(*(const __half2*)&v3.x); a0 += p.x; a1 += p.y;
        p = __half22float2(*(const __half2*)&v3.y); a2 += p.x; a3 += p.y;
    }
    for (; i < end; i++) {
        unsigned e0 = __ldg(&g_einfo[i]);
        uint2 v0 = __ldg(hrow(e0, lane));
        float2 p;
        p = __half22float2(*(const __half2*)&v0.x); a0 += p.x; a1 += p.y;
        p = __half22float2(*(const __half2*)&v0.y); a2 += p.x; a3 += p.y;
    }

    const float4 bv = __ldg((const float4*)bias + lane);
    *(float4*)(out + (size_t)node * OUT_FEAT + lane * 4) =
        make_float4(a0 + bv.x, a1 + bv.y, a2 + bv.z, a3 + bv.w);
}

// ---------------------------------------------------------------------------
// launch.  Inputs: 0:x 1:weight 2:w_comp 3:h_bias 4:src 5:dst 6:etypes
// ---------------------------------------------------------------------------
extern "C" void kernel_launch(void* const* d_in, const int* in_sizes, int n_in,
                              void* d_out, int out_size)
{
    const float* x      = (const float*)d_in[0];
    const float* weight = (const float*)d_in[1];
    const float* w_comp = (const float*)d_in[2];
    const float* bias   = (const float*)d_in[3];
    const void*  src    = d_in[4];
    const void*  dst    = d_in[5];
    const void*  et     = d_in[6];
    float* out          = (float*)d_out;

    int n_nodes = in_sizes[0] / IN_FEAT;
    int n_edges = in_sizes[4];

    cudaFuncSetAttribute(hgemm_y_kernel,
                         cudaFuncAttributeMaxDynamicSharedMemorySize, GM_SMEM_BYTES);

    detect_idx_kernel<<<1, 256>>>((const unsigned int*)src, n_edges);
    prep_WbT_kernel<<<(NB * IN_FEAT + 255) / 256, 256>>>(weight);

    // GEMM  Y = x @ WbT^T  (tensor cores)
    {
        dim3 grid(NB / 256, (n_nodes + 127) / 128);
        hgemm_y_kernel<<<grid, 256, GM_SMEM_BYTES>>>(x, n_nodes);
    }

    // CSR build
    zero_deg_kernel<<<128, 256>>>(n_nodes);
    hist_kernel<<<2048, 256>>>(dst, n_edges);
    scan_kernel<<<1, 1024>>>(n_nodes);
    fill_kernel<<<2048, 256>>>(src, dst, et, n_edges);

    // H = recombine(Y)
    recomb_kernel<<<(n_nodes + 3) / 4, 256>>>(w_comp, n_nodes);

    // out = bias + CSR-aggregated messages
    aggregate_kernel<<<(n_nodes * 32 + 255) / 256, 256>>>(bias, out, n_nodes);
}

// round 8
// speedup vs baseline: 3.1012x; 1.0652x over previous
#include <cuda_runtime.h>
#include <cuda_fp16.h>
#include <cstdint>

// ---------------------------------------------------------------------------
// RGCN layer, basis-factored, fp16 intermediates, tensor-core GEMM:
//   y[n,b,o]  = sum_i x[n,i] * weight[b,i,o]   mma.sync fp16 (single-term A)
//   H[n,r,o]  = sum_b w_comp[r,b] * y[n,b,o]   half2 recombination
//   CSR by dst, warp-per-node:  out[d] = bias + sum_{e in csr[d]} H[src_e, et_e]
// ---------------------------------------------------------------------------

#define MAX_NODES 100000
#define MAX_EDGES 3200000
#define IN_FEAT   128
#define OUT_FEAT  128
#define NUM_RELS  16
#define NUM_BASES 8
#define NCOL      (NUM_RELS * OUT_FEAT)    // 2048
#define NB        (NUM_BASES * OUT_FEAT)   // 1024

// Scratch (static __device__ globals: allocation-free rule)
__device__ __half   g_WbT[NB * IN_FEAT];               // B^T [n][k] fp16, 256 KB
__device__ __half   g_Y[(size_t)MAX_NODES * NB];       // 204.8 MB
__device__ __half   g_H[(size_t)MAX_NODES * NCOL];     // 409.6 MB
__device__ int      g_off[MAX_NODES + 1];              // CSR offsets
__device__ int      g_cursor[MAX_NODES];
__device__ unsigned g_einfo[MAX_EDGES];                // src | (etype<<20)
__device__ int      g_idx64;

// ---------------------------------------------------------------------------
// Kernel 1: detect index dtype (int64 vs int32)
// ---------------------------------------------------------------------------
__global__ void detect_idx_kernel(const unsigned int* __restrict__ srcw, int n_edges)
{
    __shared__ int nz;
    if (threadIdx.x == 0) nz = 0;
    __syncthreads();
    int samples = n_edges < 2048 ? n_edges : 2048;
    for (int i = threadIdx.x; i < samples; i += blockDim.x)
        if (srcw[2 * i + 1] != 0u) atomicOr(&nz, 1);
    __syncthreads();
    if (threadIdx.x == 0) g_idx64 = (nz == 0) ? 1 : 0;
}

// ---------------------------------------------------------------------------
// Kernel 2: WbT[n=b*128+o][k] = (half)weight[b,k,o]
// ---------------------------------------------------------------------------
__global__ void prep_WbT_kernel(const float* __restrict__ weight)
{
    int idx = blockIdx.x * blockDim.x + threadIdx.x;
    if (idx >= NB * IN_FEAT) return;
    int n = idx >> 7;
    int k = idx & 127;
    int b = n >> 7;
    int o = n & 127;
    g_WbT[idx] = __float2half_rn(weight[((b * IN_FEAT) + k) * OUT_FEAT + o]);
}

// ---------------------------------------------------------------------------
// Kernel 3: tensor-core GEMM  Y[M x 1024] = x[M x 128] @ WbT^T
// mma.sync.m16n8k16.f32.f16.f16.f32, single-rounded fp16 A.
// CTA tile 128x256, 8 warps (2m x 4n), warp tile 64x64, K=128 single shot.
// SMEM rows padded to 68 words -> conflict-free fragment LDS.
// ---------------------------------------------------------------------------
#define AST 68
#define BST 68
#define GM_SMEM_WORDS (128 * AST + 256 * BST)          // 26112
#define GM_SMEM_BYTES (GM_SMEM_WORDS * 4)              // 104448

__device__ __forceinline__ uint32_t pk(__half a, __half b)
{
    __half2 t = __halves2half2(a, b);
    return *(uint32_t*)&t;
}

__device__ __forceinline__ void mma16816(float* d, const uint32_t* a, const uint32_t* b)
{
    asm volatile(
        "mma.sync.aligned.m16n8k16.row.col.f32.f16.f16.f32 "
        "{%0,%1,%2,%3}, {%4,%5,%6,%7}, {%8,%9}, {%0,%1,%2,%3};"
        : "+f"(d[0]), "+f"(d[1]), "+f"(d[2]), "+f"(d[3])
        : "r"(a[0]), "r"(a[1]), "r"(a[2]), "r"(a[3]), "r"(b[0]), "r"(b[1]));
}

__global__ __launch_bounds__(256, 1) void hgemm_y_kernel(
    const float* __restrict__ A, int M)
{
    extern __shared__ uint32_t sh[];
    uint32_t* Ah = sh;
    uint32_t* Bw = sh + 128 * AST;

    const int tid = threadIdx.x;
    const int rowBase = blockIdx.y * 128;
    const int colBase = blockIdx.x * 256;

    // --- load A tile (128x128 fp32), round to fp16 ---
    {
        int r = tid >> 1;
        int kbase = (tid & 1) * 64;
        bool ok = (rowBase + r) < M;
        const float4* src = (const float4*)(A + (size_t)(rowBase + r) * IN_FEAT + kbase);
#pragma unroll
        for (int j = 0; j < 16; j++) {
            float4 v = make_float4(0.f, 0.f, 0.f, 0.f);
            if (ok) v = src[j];
            int w = r * AST + ((kbase + j * 4) >> 1);
            Ah[w]     = pk(__float2half_rn(v.x), __float2half_rn(v.y));
            Ah[w + 1] = pk(__float2half_rn(v.z), __float2half_rn(v.w));
        }
    }
    // --- load B tile (256 n-rows x 128 k fp16) ---
    {
        const uint4* src = (const uint4*)(g_WbT + (size_t)(colBase + tid) * IN_FEAT);
#pragma unroll
        for (int j = 0; j < 16; j++)
            *(uint4*)(Bw + tid * BST + j * 4) = src[j];
    }
    __syncthreads();

    const int lane = tid & 31;
    const int warp = tid >> 5;
    const int wm = warp & 1;            // 0..1
    const int wn = warp >> 1;           // 0..3
    const int g  = lane >> 2;           // 0..7
    const int tg = lane & 3;            // 0..3

    float acc[4][8][4];
#pragma unroll
    for (int i = 0; i < 4; i++)
#pragma unroll
        for (int j = 0; j < 8; j++)
#pragma unroll
            for (int c = 0; c < 4; c++) acc[i][j][c] = 0.f;

#pragma unroll
    for (int ks = 0; ks < 8; ks++) {
        const int kw = ks * 8;
        uint32_t bf[8][2];
#pragma unroll
        for (int nA = 0; nA < 8; nA++) {
            int n = wn * 64 + nA * 8 + g;
            bf[nA][0] = Bw[n * BST + kw + tg];
            bf[nA][1] = Bw[n * BST + kw + 4 + tg];
        }
#pragma unroll
        for (int mA = 0; mA < 4; mA++) {
            int r = wm * 64 + mA * 16 + g;
            uint32_t ah[4];
            ah[0] = Ah[r * AST + kw + tg];
            ah[1] = Ah[(r + 8) * AST + kw + tg];
            ah[2] = Ah[r * AST + kw + 4 + tg];
            ah[3] = Ah[(r + 8) * AST + kw + 4 + tg];
#pragma unroll
            for (int nA = 0; nA < 8; nA++)
                mma16816(acc[mA][nA], ah, bf[nA]);
        }
    }

    // --- epilogue: fp16 half2 stores into Y ---
    __half2* Yp = (__half2*)g_Y;
#pragma unroll
    for (int mA = 0; mA < 4; mA++) {
        int r0 = rowBase + wm * 64 + mA * 16 + g;
#pragma unroll
        for (int nA = 0; nA < 8; nA++) {
            int col = colBase + wn * 64 + nA * 8 + 2 * tg;
            if (r0 < M)
                Yp[(size_t)r0 * (NB / 2) + (col >> 1)] =
                    __floats2half2_rn(acc[mA][nA][0], acc[mA][nA][1]);
            if (r0 + 8 < M)
                Yp[(size_t)(r0 + 8) * (NB / 2) + (col >> 1)] =
                    __floats2half2_rn(acc[mA][nA][2], acc[mA][nA][3]);
        }
    }
}

// ---------------------------------------------------------------------------
// Kernel 4: half2 recombination  H[n, r, o2] = sum_b wc[r,b] * Y[n, b, o2]
// ---------------------------------------------------------------------------
__global__ __launch_bounds__(256) void recomb_kernel(const float* __restrict__ w_comp,
                                                     int M)
{
    __shared__ float wc[NUM_RELS * NUM_BASES];
    if (threadIdx.x < NUM_RELS * NUM_BASES)
        wc[threadIdx.x] = w_comp[threadIdx.x];
    __syncthreads();

    int node = blockIdx.x * 4 + (threadIdx.x >> 6);
    int op   = threadIdx.x & 63;
    if (node >= M) return;

    const __half2* y = (const __half2*)(g_Y + (size_t)node * NB) + op;
    float2 yv[NUM_BASES];
#pragma unroll
    for (int b = 0; b < NUM_BASES; b++)
        yv[b] = __half22float2(y[b * 64]);

    __half2* h = (__half2*)(g_H + (size_t)node * NCOL) + op;
#pragma unroll
    for (int r = 0; r < NUM_RELS; r++) {
        float sx = 0.f, sy = 0.f;
#pragma unroll
        for (int b = 0; b < NUM_BASES; b++) {
            float w = wc[r * NUM_BASES + b];
            sx += w * yv[b].x;
            sy += w * yv[b].y;
        }
        h[r * 64] = __floats2half2_rn(sx, sy);
    }
}

// ---------------------------------------------------------------------------
// CSR build: zero -> histogram -> single-CTA chunked scan -> fill
// ---------------------------------------------------------------------------
__global__ void zero_deg_kernel(int n_nodes)
{
    for (int i = blockIdx.x * blockDim.x + threadIdx.x; i <= n_nodes;
         i += gridDim.x * blockDim.x)
        g_off[i] = 0;
}

__global__ void hist_kernel(const void* __restrict__ dstp, int n_edges)
{
    for (int e = blockIdx.x * blockDim.x + threadIdx.x; e < n_edges;
         e += gridDim.x * blockDim.x) {
        int d = g_idx64 ? (int)((const long long*)dstp)[e] : ((const int*)dstp)[e];
        atomicAdd(&g_off[d], 1);
    }
}

__global__ __launch_bounds__(1024) void scan_kernel(int n_nodes)
{
    __shared__ int ps[1024];
    const int t = threadIdx.x;
    const int C = (n_nodes + 1023) / 1024;
    const int beg = t * C;
    const int end = min(beg + C, n_nodes);

    int sum = 0;
    for (int i = beg; i < end; i++) sum += g_off[i];
    ps[t] = sum;
    __syncthreads();

    for (int s = 1; s < 1024; s <<= 1) {
        int v = (t >= s) ? ps[t - s] : 0;
        __syncthreads();
        ps[t] += v;
        __syncthreads();
    }

    int run = (t == 0) ? 0 : ps[t - 1];
    for (int i = beg; i < end; i++) {
        int dgi = g_off[i];
        g_off[i] = run;
        g_cursor[i] = run;
        run += dgi;
    }
    if (t == 0) g_off[n_nodes] = ps[1023];
}

__global__ void fill_kernel(const void* __restrict__ srcp,
                            const void* __restrict__ dstp,
                            const void* __restrict__ etp, int n_edges)
{
    for (int e = blockIdx.x * blockDim.x + threadIdx.x; e < n_edges;
         e += gridDim.x * blockDim.x) {
        int s, d, t;
        if (g_idx64) {
            s = (int)((const long long*)srcp)[e];
            d = (int)((const long long*)dstp)[e];
            t = (int)((const long long*)etp)[e];
        } else {
            s = ((const int*)srcp)[e];
            d = ((const int*)dstp)[e];
            t = ((const int*)etp)[e];
        }
        int p = atomicAdd(&g_cursor[d], 1);
        g_einfo[p] = (unsigned)s | ((unsigned)t << 20);
    }
}

// ---------------------------------------------------------------------------
// Kernel 5: warp-per-destination aggregation, unrolled x4 for MLP.
// ---------------------------------------------------------------------------
__device__ __forceinline__ const uint2* hrow(unsigned ei, int lane)
{
    size_t off = ((size_t)(ei & 0xFFFFFu) * NUM_RELS + (ei >> 20)) * OUT_FEAT;
    return (const uint2*)(g_H + off) + lane;
}

__global__ __launch_bounds__(256) void aggregate_kernel(
    const float* __restrict__ bias, float* __restrict__ out, int M)
{
    int node = (blockIdx.x * 256 + threadIdx.x) >> 5;
    int lane = threadIdx.x & 31;
    if (node >= M) return;

    const int beg = g_off[node];
    const int end = g_off[node + 1];

    float a0 = 0.f, a1 = 0.f, a2 = 0.f, a3 = 0.f;
    int i = beg;
    for (; i + 4 <= end; i += 4) {
        unsigned e0 = __ldg(&g_einfo[i + 0]);
        unsigned e1 = __ldg(&g_einfo[i + 1]);
        unsigned e2 = __ldg(&g_einfo[i + 2]);
        unsigned e3 = __ldg(&g_einfo[i + 3]);
        uint2 v0 = __ldg(hrow(e0, lane));
        uint2 v1 = __ldg(hrow(e1, lane));
        uint2 v2 = __ldg(hrow(e2, lane));
        uint2 v3 = __ldg(hrow(e3, lane));
        float2 p;
        p = __half22float2(*(const __half2*)&v0.x); a0 += p.x; a1 += p.y;
        p = __half22float2(*(const __half2*)&v0.y); a2 += p.x; a3 += p.y;
        p = __half22float2(*(const __half2*)&v1.x); a0 += p.x; a1 += p.y;
        p = __half22float2(*(const __half2*)&v1.y); a2 += p.x; a3 += p.y;
        p = __half22float2(*(const __half2*)&v2.x); a0 += p.x; a1 += p.y;
        p = __half22float2(*(const __half2*)&v2.y); a2 += p.x; a3 += p.y;
        p = __half22float2(*(const __half2*)&v3.x); a0 += p.x; a1 += p.y;
        p = __half22float2(*(const __half2*)&v3.y); a2 += p.x; a3 += p.y;
    }
    for (; i < end; i++) {
        unsigned e0 = __ldg(&g_einfo[i]);
        uint2 v0 = __ldg(hrow(e0, lane));
        float2 p;
        p = __half22float2(*(const __half2*)&v0.x); a0 += p.x; a1 += p.y;
        p = __half22float2(*(const __half2*)&v0.y); a2 += p.x; a3 += p.y;
    }

    const float4 bv = __ldg((const float4*)bias + lane);
    *(float4*)(out + (size_t)node * OUT_FEAT + lane * 4) =
        make_float4(a0 + bv.x, a1 + bv.y, a2 + bv.z, a3 + bv.w);
}

// ---------------------------------------------------------------------------
// launch.  Inputs: 0:x 1:weight 2:w_comp 3:h_bias 4:src 5:dst 6:etypes
// ---------------------------------------------------------------------------
extern "C" void kernel_launch(void* const* d_in, const int* in_sizes, int n_in,
                              void* d_out, int out_size)
{
    const float* x      = (const float*)d_in[0];
    const float* weight = (const float*)d_in[1];
    const float* w_comp = (const float*)d_in[2];
    const float* bias   = (const float*)d_in[3];
    const void*  src    = d_in[4];
    const void*  dst    = d_in[5];
    const void*  et     = d_in[6];
    float* out          = (float*)d_out;

    int n_nodes = in_sizes[0] / IN_FEAT;
    int n_edges = in_sizes[4];

    cudaFuncSetAttribute(hgemm_y_kernel,
                         cudaFuncAttributeMaxDynamicSharedMemorySize, GM_SMEM_BYTES);

    detect_idx_kernel<<<1, 256>>>((const unsigned int*)src, n_edges);
    prep_WbT_kernel<<<(NB * IN_FEAT + 255) / 256, 256>>>(weight);

    // GEMM  Y = x @ WbT^T  (tensor cores)
    {
        dim3 grid(NB / 256, (n_nodes + 127) / 128);
        hgemm_y_kernel<<<grid, 256, GM_SMEM_BYTES>>>(x, n_nodes);
    }

    // CSR build
    zero_deg_kernel<<<128, 256>>>(n_nodes);
    hist_kernel<<<2048, 256>>>(dst, n_edges);
    scan_kernel<<<1, 1024>>>(n_nodes);
    fill_kernel<<<2048, 256>>>(src, dst, et, n_edges);

    // H = recombine(Y)
    recomb_kernel<<<(n_nodes + 3) / 4, 256>>>(w_comp, n_nodes);

    // out = bias + CSR-aggregated messages
    aggregate_kernel<<<(n_nodes * 32 + 255) / 256, 256>>>(bias, out, n_nodes);
}